// round 13
// baseline (speedup 1.0000x reference)
#include <cuda_runtime.h>
#include <cstdint>
#include <math.h>

// Problem constants (dataset: B=65536, D=256, K=10)
#define KK 10
#define DD 256
#define TROWS 64              // rows per tile (4 warps x 8 slots x R=2)
#define GRID_MAIN 592         // 4 blocks/SM
#define L2PI_F 1.8378770664093453f
#define MARGIN 0.02f

typedef unsigned long long ull;

// ---- device globals ----
__device__ int g_tile;            // tile counter; memset to 0 each run

// ---------- packed f32x2 helpers ----------
static __device__ __forceinline__ ull pack2(float x, float y) {
    ull r; asm("mov.b64 %0, {%1, %2};" : "=l"(r) : "f"(x), "f"(y)); return r;
}
static __device__ __forceinline__ void unpack2(ull v, float& x, float& y) {
    asm("mov.b64 {%0, %1}, %2;" : "=f"(x), "=f"(y) : "l"(v));
}
static __device__ __forceinline__ ull fma2(ull a, ull b, ull c) {
    ull d; asm("fma.rn.f32x2 %0, %1, %2, %3;" : "=l"(d) : "l"(a), "l"(b), "l"(c)); return d;
}
static __device__ __forceinline__ ull add2(ull a, ull b) {
    ull d; asm("add.rn.f32x2 %0, %1, %2;" : "=l"(d) : "l"(a), "l"(b)); return d;
}
static __device__ __forceinline__ ull mul2(ull a, ull b) {
    ull d; asm("mul.rn.f32x2 %0, %1, %2;" : "=l"(d) : "l"(a), "l"(b)); return d;
}

// ================== single fused persistent kernel ==================
__global__ void __launch_bounds__(128, 4)
k_fused(const float* __restrict__ q, const float* __restrict__ mu,
        const float* __restrict__ lv,
        float* __restrict__ out_logit, float* __restrict__ out_qy,
        float* __restrict__ out_ind, int nrows)
{
    // cheap coef table: ulonglong2 idx ((2g+h)*5+kp)*4+s
    __shared__ __align__(16) ulonglong2 s_cb[640];      // 10240 B
    // exact-path tables, k-interleaved (p*KK+k): conflict-free k-fan
    __shared__ __align__(16) ull s_nm[128 * KK];        // 10240 B
    __shared__ __align__(16) ull s_lv[128 * KK];        // 10240 B
    __shared__ __align__(16) ull s_q[4][128];           // 4096 B (fix: 1 row/warp)
    __shared__ float s_Cpart[KK][8];
    __shared__ float s_C[KK];
    __shared__ int   s_nz, s_tile, s_cnt;
    __shared__ int   s_list[TROWS];

    const int t = threadIdx.x;
    const int lane = t & 31, warp = t >> 5;
    if (t == 0) s_nz = 0;
    __syncthreads();

    // ---------- block prep (once): cheap coefs + exact tables + C_k ----------
    int any = 0;
    #pragma unroll
    for (int i = 0; i < 5; i++) {
        int e = t + 128 * i;
        int s  = e & 3;
        int rest = e >> 2;
        int kp = rest % 5;
        int gh = rest / 5;
        int h = gh & 1, g = gh >> 1;
        int pair = 8 * g + 2 * s + h, d = 2 * pair;
        int k0 = 2 * kp, k1 = 2 * kp + 1;
        float l00 = lv[k0 * DD + d], l01 = lv[k0 * DD + d + 1];
        float l10 = lv[k1 * DD + d], l11 = lv[k1 * DD + d + 1];
        float m00 = mu[k0 * DD + d], m01 = mu[k0 * DD + d + 1];
        float m10 = mu[k1 * DD + d], m11 = mu[k1 * DD + d + 1];
        ulonglong2 u;
        u.x = pack2(-2.0f * __expf(-l00) * m00, -2.0f * __expf(-l01) * m01);
        u.y = pack2(-2.0f * __expf(-l10) * m10, -2.0f * __expf(-l11) * m11);
        s_cb[e] = u;
        if (l00 != 0.0f || l01 != 0.0f || l10 != 0.0f || l11 != 0.0f) any = 1;
    }
    #pragma unroll
    for (int i = 0; i < KK; i++) {                   // exact tables (sign flip only)
        int ix = t + 128 * i;
        int p = ix / KK, k = ix % KK, d = 2 * p;
        float m0 = mu[k * DD + d], m1 = mu[k * DD + d + 1];
        float l0 = lv[k * DD + d], l1 = lv[k * DD + d + 1];
        s_nm[p * KK + k] = pack2(-m0, -m1);
        s_lv[p * KK + k] = pack2(l0, l1);
    }
    if (any) atomicOr(&s_nz, 1);
    if (t < 80) {
        int k = t >> 3, part = t & 7;
        float s = 0.0f;
        #pragma unroll 4
        for (int j = 0; j < 32; j++) {
            int d = part * 32 + j;
            float l = lv[k * DD + d], m = mu[k * DD + d];
            s += __fmaf_rn(__expf(-l) * m, m, l) + L2PI_F;
        }
        s_Cpart[k][part] = s;
    }
    __syncthreads();
    if (t < KK) {
        float tot = 0.0f;
        #pragma unroll
        for (int j = 0; j < 8; j++) tot += s_Cpart[t][j];
        float logk0 = (float)log((double)(1.0f / (float)KK));
        s_C[t] = __fmaf_rn(-0.5f, tot, logk0);
    }
    __syncthreads();
    const int fast = (s_nz == 0);
    const float logk = (float)log((double)(1.0f / (float)KK));
    const ull L2 = pack2(L2PI_F, L2PI_F);

    const int s = lane & 3, r = lane >> 2;           // main: lane sub / row-slot
    const int kk = (lane < 20) ? (lane >> 1) : 0;    // fix: component per lane
    const int h  = lane & 1;                         // fix: w4 parity
    const int nt = (nrows + TROWS - 1) / TROWS;

    for (;;) {
        __syncthreads();                             // protect s_tile/s_cnt reuse
        if (t == 0) { s_tile = atomicAdd(&g_tile, 1); s_cnt = 0; }
        __syncthreads();
        const int tile = s_tile;
        if (tile >= nt) break;

        // ---------- main: R=2 rows/thread, depth-4 LDG pipeline ----------
        const int rA = tile * TROWS + warp * 16 + r;
        const int rB = rA + 8;
        const float4* qpA = reinterpret_cast<const float4*>(q)
                          + (size_t)((rA < nrows) ? rA : 0) * 64 + s;
        const float4* qpB = reinterpret_cast<const float4*>(q)
                          + (size_t)((rB < nrows) ? rB : 0) * 64 + s;

        ull accA[KK], accB[KK];
        #pragma unroll
        for (int k = 0; k < KK; k++) { accA[k] = 0ull; accB[k] = 0ull; }
        ull S2A = 0ull, S2B = 0ull;

        float4 bufA[4], bufB[4];
        #pragma unroll
        for (int j = 0; j < 4; j++) { bufA[j] = __ldg(qpA + 4 * j); bufB[j] = __ldg(qpB + 4 * j); }

        #pragma unroll
        for (int g = 0; g < 16; g++) {
            float4 vA = bufA[g & 3], vB = bufB[g & 3];
            if (g + 4 < 16) {
                bufA[g & 3] = __ldg(qpA + 4 * (g + 4));
                bufB[g & 3] = __ldg(qpB + 4 * (g + 4));
            }
            ull qa0 = pack2(vA.x, vA.y), qa1 = pack2(vA.z, vA.w);
            ull qb0 = pack2(vB.x, vB.y), qb1 = pack2(vB.z, vB.w);
            S2A = fma2(qa0, qa0, S2A); S2A = fma2(qa1, qa1, S2A);
            S2B = fma2(qb0, qb0, S2B); S2B = fma2(qb1, qb1, S2B);
            const int b0 = (2 * g) * 20 + s;
            const int b1 = (2 * g + 1) * 20 + s;
            #pragma unroll
            for (int kp = 0; kp < 5; kp++) {
                ulonglong2 c0 = s_cb[b0 + 4 * kp];
                accA[2 * kp]     = fma2(c0.x, qa0, accA[2 * kp]);
                accA[2 * kp + 1] = fma2(c0.y, qa0, accA[2 * kp + 1]);
                accB[2 * kp]     = fma2(c0.x, qb0, accB[2 * kp]);
                accB[2 * kp + 1] = fma2(c0.y, qb0, accB[2 * kp + 1]);
                ulonglong2 c1 = s_cb[b1 + 4 * kp];
                accA[2 * kp]     = fma2(c1.x, qa1, accA[2 * kp]);
                accA[2 * kp + 1] = fma2(c1.y, qa1, accA[2 * kp + 1]);
                accB[2 * kp]     = fma2(c1.x, qb1, accB[2 * kp]);
                accB[2 * kp + 1] = fma2(c1.y, qb1, accB[2 * kp + 1]);
            }
        }

        #pragma unroll
        for (int k = 0; k < KK; k++) {
            accA[k] = add2(accA[k], __shfl_xor_sync(0xffffffffu, accA[k], 1));
            accA[k] = add2(accA[k], __shfl_xor_sync(0xffffffffu, accA[k], 2));
            accB[k] = add2(accB[k], __shfl_xor_sync(0xffffffffu, accB[k], 1));
            accB[k] = add2(accB[k], __shfl_xor_sync(0xffffffffu, accB[k], 2));
        }
        S2A = add2(S2A, __shfl_xor_sync(0xffffffffu, S2A, 1));
        S2A = add2(S2A, __shfl_xor_sync(0xffffffffu, S2A, 2));
        S2B = add2(S2B, __shfl_xor_sync(0xffffffffu, S2B, 1));
        S2B = add2(S2B, __shfl_xor_sync(0xffffffffu, S2B, 2));

        if (s == 0) {
            #pragma unroll
            for (int j = 0; j < 2; j++) {
                const int row = (j == 0) ? rA : rB;
                if (row < nrows) {
                    const ull* acc = (j == 0) ? accA : accB;
                    ull S2v = (j == 0) ? S2A : S2B;
                    float s2f;
                    { float lo, hi; unpack2(S2v, lo, hi); s2f = lo + hi; }
                    float l[KK];
                    #pragma unroll
                    for (int k = 0; k < KK; k++) {
                        float lo, hi; unpack2(acc[k], lo, hi);
                        l[k] = __fmaf_rn(-0.5f, (lo + hi) + s2f, s_C[k]);
                    }
                    float t1 = l[0], t2 = -3.4e38f;
                    #pragma unroll
                    for (int k = 1; k < KK; k++) {
                        float v = l[k];
                        if (v > t1) { t2 = t1; t1 = v; } else if (v > t2) t2 = v;
                    }
                    float e[KK], ssum = 0.0f;
                    #pragma unroll
                    for (int k = 0; k < KK; k++) { e[k] = __expf(l[k] - t1); ssum += e[k]; }
                    float inv = 1.0f / ssum;
                    float2* lo2 = reinterpret_cast<float2*>(out_logit + (size_t)row * KK);
                    float2* qo2 = reinterpret_cast<float2*>(out_qy    + (size_t)row * KK);
                    #pragma unroll
                    for (int i = 0; i < KK / 2; i++) {
                        lo2[i] = make_float2(l[2 * i], l[2 * i + 1]);
                        qo2[i] = make_float2(e[2 * i] * inv, e[2 * i + 1] * inv);
                    }
                    int best = 0; float bv = l[0];
                    #pragma unroll
                    for (int k = 1; k < KK; k++) if (l[k] > bv) { bv = l[k]; best = k; }
                    out_ind[row] = (float)best;
                    if ((!fast) | (t1 - t2 < MARGIN)) {
                        int ix = atomicAdd(&s_cnt, 1);
                        s_list[ix] = row;
                    }
                }
            }
        }
        __syncthreads();

        // ---------- in-tile exact fix: warp per flagged row, lanes over (k,h) ----------
        const int cnt = s_cnt;
        for (int i = warp; i < cnt; i += 4) {
            const int rr = s_list[i];
            {   // stage row q: coalesced, 2 float4 per lane
                const float4* q4 = reinterpret_cast<const float4*>(q + (size_t)rr * DD);
                float4 v0 = __ldg(q4 + lane);
                float4 v1 = __ldg(q4 + lane + 32);
                s_q[warp][2 * lane]            = pack2(v0.x, v0.y);
                s_q[warp][2 * lane + 1]        = pack2(v0.z, v0.w);
                s_q[warp][2 * (lane + 32)]     = pack2(v1.x, v1.y);
                s_q[warp][2 * (lane + 32) + 1] = pack2(v1.z, v1.w);
            }
            __syncwarp();

            float Wv[2];
            #pragma unroll
            for (int t2 = 0; t2 < 2; t2++) {
                const int w4 = h + 2 * t2;
                float a[16];
                if (fast) {
                    #pragma unroll
                    for (int l = 0; l < 16; l++) {
                        int p1 = w4 * 32 + l, p2 = p1 + 16;
                        ull f1 = add2(s_q[warp][p1], s_nm[p1 * KK + kk]);  // fl(q-mu)
                        ull u1 = add2(mul2(f1, f1), L2);                   // fl(fl(d^2)+L2PI)
                        ull f2 = add2(s_q[warp][p2], s_nm[p2 * KK + kk]);
                        ull u2 = add2(mul2(f2, f2), L2);
                        float x1, y1, x2, y2;
                        unpack2(u1, x1, y1); unpack2(u2, x2, y2);
                        // a_l = fl( s_l + s_{l+16} ), s = fl(u_even + u_odd)
                        a[l] = __fadd_rn(__fadd_rn(x1, y1), __fadd_rn(x2, y2));
                    }
                } else {
                    #pragma unroll
                    for (int l = 0; l < 16; l++) {
                        float s12[2];
                        #pragma unroll
                        for (int hh = 0; hh < 2; hh++) {
                            int p = w4 * 32 + l + 16 * hh;
                            float q0, q1, n0, n1, v0, v1;
                            unpack2(s_q[warp][p], q0, q1);
                            unpack2(s_nm[p * KK + kk], n0, n1);
                            unpack2(s_lv[p * KK + kk], v0, v1);
                            float e0 = (v0 == 0.0f) ? 1.0f : expf(v0);
                            float e1 = (v1 == 0.0f) ? 1.0f : expf(v1);
                            float f0 = __fadd_rn(q0, n0), f1 = __fadd_rn(q1, n1);
                            float u0 = __fadd_rn(__fadd_rn(
                                __fdiv_rn(__fmul_rn(f0, f0), e0), v0), L2PI_F);
                            float u1 = __fadd_rn(__fadd_rn(
                                __fdiv_rn(__fmul_rn(f1, f1), e1), v1), L2PI_F);
                            s12[hh] = __fadd_rn(u0, u1);
                        }
                        a[l] = __fadd_rn(s12[0], s12[1]);
                    }
                }
                float bb[8];
                #pragma unroll
                for (int l = 0; l < 8; l++) bb[l] = __fadd_rn(a[l], a[l + 8]);
                float cc[4];
                #pragma unroll
                for (int l = 0; l < 4; l++) cc[l] = __fadd_rn(bb[l], bb[l + 4]);
                float d0 = __fadd_rn(cc[0], cc[2]);
                float d1 = __fadd_rn(cc[1], cc[3]);
                Wv[t2] = __fadd_rn(d0, d1);
            }
            float sum2 = __fadd_rn(Wv[0], Wv[1]);          // h=0: W0+W2 ; h=1: W1+W3
            float s_other = __shfl_down_sync(0xffffffffu, sum2, 1);
            float L = __fadd_rn(sum2, s_other);            // valid at even lanes
            float lgt = __fadd_rn(__fmul_rn(-0.5f, L), logk);

            float l10[KK];
            #pragma unroll
            for (int k = 0; k < KK; k++)
                l10[k] = __shfl_sync(0xffffffffu, lgt, 2 * k);

            if (lane == 0) {
                float m = l10[0];
                #pragma unroll
                for (int k = 1; k < KK; k++) m = fmaxf(m, l10[k]);
                float e[KK];
                #pragma unroll
                for (int k = 0; k < KK; k++) e[k] = expf(__fadd_rn(l10[k], -m));
                float s0 = __fadd_rn(__fadd_rn(__fadd_rn(e[0], e[8]), e[4]),
                                     __fadd_rn(e[2], e[6]));
                float s1 = __fadd_rn(__fadd_rn(__fadd_rn(e[1], e[9]), e[5]),
                                     __fadd_rn(e[3], e[7]));
                float ssum = __fadd_rn(s0, s1);
                float qv[KK];
                #pragma unroll
                for (int k = 0; k < KK; k++) qv[k] = __fdiv_rn(e[k], ssum);
                #pragma unroll
                for (int k = 0; k < KK; k++) {
                    out_logit[(size_t)rr * KK + k] = l10[k];
                    out_qy   [(size_t)rr * KK + k] = qv[k];
                }
                int best = 0; float bv = qv[0];
                #pragma unroll
                for (int k = 1; k < KK; k++)
                    if (qv[k] > bv) { bv = qv[k]; best = k; }
                out_ind[rr] = (float)best;
            }
            __syncwarp();
        }
    }
}

extern "C" void kernel_launch(void* const* d_in, const int* in_sizes, int n_in,
                              void* d_out, int out_size) {
    const float* q_z = (const float*)d_in[0];   // [B, 256]
    const float* mu  = (const float*)d_in[1];   // [10, 256]
    const float* lv  = (const float*)d_in[2];   // [10, 256]

    int nrows = in_sizes[0] / DD;

    float* out_logit = (float*)d_out;                    // [B, 10]
    float* out_qy    = out_logit + (size_t)nrows * KK;   // [B, 10]
    float* out_ind   = out_qy    + (size_t)nrows * KK;   // [B]

    // reset tile counter (graph-capturable memset node; no alloc, no sync)
    void* tp = nullptr;
    cudaGetSymbolAddress(&tp, g_tile);
    cudaMemsetAsync(tp, 0, sizeof(int));

    int nt = (nrows + TROWS - 1) / TROWS;
    int grid = (nt < GRID_MAIN) ? nt : GRID_MAIN;
    k_fused<<<grid, 128>>>(q_z, mu, lv, out_logit, out_qy, out_ind, nrows);
}